// round 3
// baseline (speedup 1.0000x reference)
#include <cuda_runtime.h>
#include <math.h>

#define BB 16
#define DD 256
#define TT 4096
#define NN (BB*TT)      // 65536 rows
#define KK 1024         // codes
#define ROWS 128        // rows per CTA
#define KTILE 128       // codes per k-tile
#define DC 32           // d-chunk
#define NTH 256
#define PAD 132         // padded tile row (float4-aligned)

#define OUT_LOSS ((size_t)NN*DD)     // 16777216
#define OUT_PERP (OUT_LOSS+1)
#define OUT_IDX  (OUT_PERP+1)

__device__ float  g_wnorm[KK];
__device__ float  g_xnorm[NN];
__device__ int    g_counts[KK];
__device__ double g_acc;

// ---------------- xnorm: per-row sum(x^2) with candidate reduction orders ----
// A: GPU warp-reduce (32 lanes stride 32, shfl_down tree)     rows [0,32768)
// B: NEON 4-lane stride 4, LLVM halving horizontal            rows [32768,49152)
// C: scalar sequential                                        rows [49152,57344)
// D: NEON 2x-unrolled: 8 lanes stride 8, fold+halving         rows [57344,65536)
__global__ __launch_bounds__(256) void vq_xnorm(const float* __restrict__ x) {
    int r = blockIdx.x * blockDim.x + threadIdx.x;     // 0..65535
    int b = r >> 12, t = r & 4095;
    const float* xp = x + (size_t)b * (DD * TT) + t;
    float pA[32], pB[4], pD[8], seq = 0.f;
    #pragma unroll
    for (int l = 0; l < 32; l++) pA[l] = 0.f;
    #pragma unroll
    for (int l = 0; l < 4; l++) pB[l] = 0.f;
    #pragma unroll
    for (int l = 0; l < 8; l++) pD[l] = 0.f;
    #pragma unroll 1
    for (int i = 0; i < 8; i++) {
        #pragma unroll
        for (int l = 0; l < 32; l++) {
            float v = __ldg(&xp[(size_t)(i * 32 + l) * TT]);
            float sq = __fmul_rn(v, v);
            pA[l]     = __fadd_rn(pA[l], sq);
            pB[l & 3] = __fadd_rn(pB[l & 3], sq);
            pD[l & 7] = __fadd_rn(pD[l & 7], sq);
            seq       = __fadd_rn(seq, sq);
        }
    }
    // A: shfl_down tree 16/8/4/2/1 (lane0 path)
    #pragma unroll
    for (int l = 0; l < 16; l++) pA[l] = __fadd_rn(pA[l], pA[l + 16]);
    #pragma unroll
    for (int l = 0; l < 8; l++)  pA[l] = __fadd_rn(pA[l], pA[l + 8]);
    #pragma unroll
    for (int l = 0; l < 4; l++)  pA[l] = __fadd_rn(pA[l], pA[l + 4]);
    pA[0] = __fadd_rn(pA[0], pA[2]); pA[1] = __fadd_rn(pA[1], pA[3]);
    float xnA = __fadd_rn(pA[0], pA[1]);
    // B: halving shuffle on 4 lanes: (p0+p2)+(p1+p3)
    float xnB = __fadd_rn(__fadd_rn(pB[0], pB[2]), __fadd_rn(pB[1], pB[3]));
    // C: sequential
    float xnC = seq;
    // D: fold 8->4 then halving
    #pragma unroll
    for (int l = 0; l < 4; l++) pD[l] = __fadd_rn(pD[l], pD[l + 4]);
    float xnD = __fadd_rn(__fadd_rn(pD[0], pD[2]), __fadd_rn(pD[1], pD[3]));

    float xn = (r < 32768) ? xnA : (r < 49152) ? xnB : (r < 57344) ? xnC : xnD;
    g_xnorm[r] = xn;
}

// ---------------- prep: wnorm (order-insensitive), zero counts/acc ----------
__global__ void vq_prep(const float* __restrict__ w) {
    int gt   = blockIdx.x * blockDim.x + threadIdx.x;
    int warp = gt >> 5, lane = gt & 31;
    const float* wr = w + (size_t)warp * DD;
    float s = 0.f;
    #pragma unroll
    for (int d = lane; d < DD; d += 32) { float v = wr[d]; s = __fmaf_rn(v, v, s); }
    #pragma unroll
    for (int o = 16; o; o >>= 1) s = __fadd_rn(s, __shfl_xor_sync(0xffffffffu, s, o));
    if (lane == 0) g_wnorm[warp] = s;
    if (gt < KK) g_counts[gt] = 0;
    if (gt == 0) g_acc = 0.0;
}

// ---------------- main: distance GEMM + argmin + gather ----------------
struct Smem {
    float xs[DC][PAD];
    union {
        float ws[DC][PAD];
        struct { float S[ROWS][16]; int I[ROWS][16]; } red;
    } u;
    float bestS[ROWS];
    int   bestI[ROWS];
    float rbuf[8];
};

__global__ __launch_bounds__(NTH) void vq_main(const float* __restrict__ x,
                                               const float* __restrict__ w,
                                               float* __restrict__ out) {
    __shared__ Smem sm;
    int tid = threadIdx.x;
    int cta = blockIdx.x;                    // 512 CTAs
    int b   = cta >> 5;
    int t0  = (cta & 31) * ROWS;
    const float* xb = x + (size_t)b * DD * TT + t0;
    int tr = tid & 15;                       // rows 8*tr..8*tr+7
    int tc = tid >> 4;                       // codes 8*tc..8*tc+7

    if (tid < ROWS) { sm.bestS[tid] = INFINITY; sm.bestI[tid] = 0; }

    float xnr[8];
    #pragma unroll
    for (int i = 0; i < 8; i++)
        xnr[i] = g_xnorm[(size_t)b * TT + t0 + 8 * tr + i];

    for (int kt = 0; kt < KK; kt += KTILE) {
        float acc[8][8];
        #pragma unroll
        for (int i = 0; i < 8; i++)
            #pragma unroll
            for (int j = 0; j < 8; j++) acc[i][j] = 0.f;

        for (int dc = 0; dc < DD; dc += DC) {
            __syncthreads();
            #pragma unroll
            for (int i = 0; i < (DC * ROWS) / NTH; i++) {
                int idx = tid + i * NTH;
                int d = idx >> 7, r = idx & 127;
                sm.xs[d][r] = __ldg(&xb[(size_t)(dc + d) * TT + r]);
            }
            #pragma unroll
            for (int i = 0; i < (DC * KTILE) / NTH; i++) {
                int idx = tid + i * NTH;
                int kk2 = idx >> 5, d = idx & 31;
                sm.u.ws[d][kk2] = __ldg(&w[(size_t)(kt + kk2) * DD + dc + d]);
            }
            __syncthreads();
            #pragma unroll
            for (int d = 0; d < DC; d++) {
                float4 a0 = *(const float4*)&sm.xs[d][8 * tr];
                float4 a1 = *(const float4*)&sm.xs[d][8 * tr + 4];
                float4 b0 = *(const float4*)&sm.u.ws[d][8 * tc];
                float4 b1 = *(const float4*)&sm.u.ws[d][8 * tc + 4];
                float xr[8]  = {a0.x, a0.y, a0.z, a0.w, a1.x, a1.y, a1.z, a1.w};
                float wr8[8] = {b0.x, b0.y, b0.z, b0.w, b1.x, b1.y, b1.z, b1.w};
                #pragma unroll
                for (int i = 0; i < 8; i++)
                    #pragma unroll
                    for (int j = 0; j < 8; j++)
                        acc[i][j] = __fmaf_rn(xr[i], wr8[j], acc[i][j]);
            }
        }
        __syncthreads();   // acc done; safe to overlay red onto ws

        float wn8[8];
        #pragma unroll
        for (int j = 0; j < 8; j++) wn8[j] = g_wnorm[kt + 8 * tc + j];

        // dist = fl(fl(xn + wn) - 2*dot), exactly as reference rounds it
        #pragma unroll
        for (int i = 0; i < 8; i++) {
            float bs = INFINITY; int bi = kt + 8 * tc;
            #pragma unroll
            for (int j = 0; j < 8; j++) {
                int k = kt + 8 * tc + j;
                float t1 = __fadd_rn(xnr[i], wn8[j]);
                float s  = __fmaf_rn(-2.f, acc[i][j], t1);
                if (s < bs) { bs = s; bi = k; }
            }
            sm.u.red.S[8 * tr + i][tc] = bs;
            sm.u.red.I[8 * tr + i][tc] = bi;
        }
        __syncthreads();
        if (tid < ROWS) {
            float bs = sm.bestS[tid]; int bi = sm.bestI[tid];
            #pragma unroll
            for (int c = 0; c < 16; c++) {
                float s = sm.u.red.S[tid][c]; int ii = sm.u.red.I[tid][c];
                if (s < bs || (s == bs && ii < bi)) { bs = s; bi = ii; }
            }
            sm.bestS[tid] = bs; sm.bestI[tid] = bi;
        }
        __syncthreads();
    }

    // loss partial: bestS IS the row's sum (q-x)^2 (= xn + wn - 2 x.w)
    float part = (tid < ROWS) ? sm.bestS[tid] : 0.f;
    #pragma unroll
    for (int o = 16; o; o >>= 1) part += __shfl_xor_sync(0xffffffffu, part, o);
    if ((tid & 31) == 0) sm.rbuf[tid >> 5] = part;
    __syncthreads();
    if (tid == 0) {
        float s = 0.f;
        #pragma unroll
        for (int i = 0; i < 8; i++) s += sm.rbuf[i];
        atomicAdd(&g_acc, (double)s);
    }
    if (tid < ROWS) {
        int bi = sm.bestI[tid];
        atomicAdd(&g_counts[bi], 1);
        out[OUT_IDX + (size_t)(b * TT + t0 + tid)] = (float)bi;
    }
    #pragma unroll 4
    for (int i = tid; i < ROWS * DD; i += NTH) {
        int r = i >> 8, d = i & 255;
        out[((size_t)(b * TT + t0 + r)) * DD + d] = w[(size_t)sm.bestI[r] * DD + d];
    }
}

// ---------------- finalize: loss + perplexity ----------------
__global__ void vq_final(float* __restrict__ out) {
    __shared__ float sh[32];
    int tid = threadIdx.x;    // 1024 threads, one per code
    float p = (float)g_counts[tid] / (float)NN;
    float t = p * logf(p + 1e-10f);
    #pragma unroll
    for (int o = 16; o; o >>= 1) t += __shfl_xor_sync(0xffffffffu, t, o);
    if ((tid & 31) == 0) sh[tid >> 5] = t;
    __syncthreads();
    if (tid < 32) {
        float v = sh[tid];
        #pragma unroll
        for (int o = 16; o; o >>= 1) v += __shfl_xor_sync(0xffffffffu, v, o);
        if (tid == 0) {
            out[OUT_PERP] = expf(-v);
            out[OUT_LOSS] = (float)(1.25 * g_acc / ((double)NN * (double)DD));
        }
    }
}

extern "C" void kernel_launch(void* const* d_in, const int* in_sizes, int n_in,
                              void* d_out, int out_size) {
    const float* x = (const float*)d_in[0];   // [16, 256, 4096] fp32
    const float* w = (const float*)d_in[1];   // [1024, 256] fp32
    float* out = (float*)d_out;
    vq_xnorm<<<NN / 256, 256>>>(x);           // per-row ||x||^2, 4 candidate orders
    vq_prep<<<(KK * 32) / NTH, NTH>>>(w);     // wnorm + zero scratch
    vq_main<<<NN / ROWS, NTH>>>(x, w, out);   // 512 blocks
    vq_final<<<1, KK>>>(out);
}

// round 5
// speedup vs baseline: 1.0395x; 1.0395x over previous
#include <cuda_runtime.h>
#include <math.h>

#define BB 16
#define DD 256
#define TT 4096
#define NN (BB*TT)      // 65536 rows
#define KK 1024         // codes
#define ROWS 128        // rows per CTA
#define KTILE 128       // codes per k-tile
#define DC 32           // d-chunk
#define NTH 256
#define PAD 132         // padded tile row (float4-aligned)

#define OUT_LOSS ((size_t)NN*DD)     // 16777216
#define OUT_PERP (OUT_LOSS+1)
#define OUT_IDX  (OUT_PERP+1)

typedef unsigned long long ull;

__device__ float  g_wnorm[KK];
__device__ float  g_xnorm[NN];
__device__ int    g_counts[KK];
__device__ double g_acc;

__device__ __forceinline__ ull pack2(float lo, float hi) {
    ull r; asm("mov.b64 %0, {%1,%2};" : "=l"(r) : "f"(lo), "f"(hi)); return r;
}
__device__ __forceinline__ void ffma2(ull& acc, ull a, ull b) {
    asm("fma.rn.f32x2 %0, %1, %2, %0;" : "+l"(acc) : "l"(a), "l"(b));
}
__device__ __forceinline__ void unpack2(ull v, float& lo, float& hi) {
    asm("mov.b64 {%0,%1}, %2;" : "=f"(lo), "=f"(hi) : "l"(v));
}

// ---------------- xnorm: per-row sum(x^2), GPU warp-reduce order (A) --------
__global__ __launch_bounds__(256) void vq_xnorm(const float* __restrict__ x) {
    int r = blockIdx.x * blockDim.x + threadIdx.x;     // 0..65535
    int b = r >> 12, t = r & 4095;
    const float* xp = x + (size_t)b * (DD * TT) + t;
    float pA[32];
    #pragma unroll
    for (int l = 0; l < 32; l++) pA[l] = 0.f;
    #pragma unroll 1
    for (int i = 0; i < 8; i++) {
        #pragma unroll
        for (int l = 0; l < 32; l++) {
            float v = __ldg(&xp[(size_t)(i * 32 + l) * TT]);
            pA[l] = __fadd_rn(pA[l], __fmul_rn(v, v));
        }
    }
    // shfl_down tree 16/8/4/2/1 (lane0 path)
    #pragma unroll
    for (int l = 0; l < 16; l++) pA[l] = __fadd_rn(pA[l], pA[l + 16]);
    #pragma unroll
    for (int l = 0; l < 8; l++)  pA[l] = __fadd_rn(pA[l], pA[l + 8]);
    #pragma unroll
    for (int l = 0; l < 4; l++)  pA[l] = __fadd_rn(pA[l], pA[l + 4]);
    pA[0] = __fadd_rn(pA[0], pA[2]); pA[1] = __fadd_rn(pA[1], pA[3]);
    g_xnorm[r] = __fadd_rn(pA[0], pA[1]);
}

// ---------------- prep: wnorm, zero counts/acc ----------------
__global__ void vq_prep(const float* __restrict__ w) {
    int gt   = blockIdx.x * blockDim.x + threadIdx.x;
    int warp = gt >> 5, lane = gt & 31;
    const float* wr = w + (size_t)warp * DD;
    float s = 0.f;
    #pragma unroll
    for (int d = lane; d < DD; d += 32) { float v = wr[d]; s = __fmaf_rn(v, v, s); }
    #pragma unroll
    for (int o = 16; o; o >>= 1) s = __fadd_rn(s, __shfl_xor_sync(0xffffffffu, s, o));
    if (lane == 0) g_wnorm[warp] = s;
    if (gt < KK) g_counts[gt] = 0;
    if (gt == 0) g_acc = 0.0;
}

// ---------------- main: distance GEMM (f32x2 packed) + argmin + gather -----
struct Smem {
    float xs[DC][PAD];
    union {
        float ws[DC][PAD];
        struct { float S[ROWS][16]; int I[ROWS][16]; } red;
    } u;
    float bestS[ROWS];
    int   bestI[ROWS];
    float rbuf[8];
};

__global__ __launch_bounds__(NTH) void vq_main(const float* __restrict__ x,
                                               const float* __restrict__ w,
                                               float* __restrict__ out) {
    __shared__ Smem sm;
    int tid = threadIdx.x;
    int cta = blockIdx.x;                    // 512 CTAs
    int b   = cta >> 5;
    int t0  = (cta & 31) * ROWS;
    const float* xb = x + (size_t)b * DD * TT + t0;
    int tr = tid & 15;                       // rows 8*tr..8*tr+7
    int tc = tid >> 4;                       // codes 8*tc..8*tc+7

    if (tid < ROWS) { sm.bestS[tid] = INFINITY; sm.bestI[tid] = 0; }

    float xnr[8];
    #pragma unroll
    for (int i = 0; i < 8; i++)
        xnr[i] = g_xnorm[(size_t)b * TT + t0 + 8 * tr + i];

    for (int kt = 0; kt < KK; kt += KTILE) {
        // acc2[ip][j]: row-pair (2*ip, 2*ip+1) x code j, packed fp32x2
        ull acc2[4][8];
        #pragma unroll
        for (int ip = 0; ip < 4; ip++)
            #pragma unroll
            for (int j = 0; j < 8; j++) acc2[ip][j] = 0ull;

        for (int dc = 0; dc < DD; dc += DC) {
            __syncthreads();
            #pragma unroll
            for (int i = 0; i < (DC * ROWS) / NTH; i++) {
                int idx = tid + i * NTH;
                int d = idx >> 7, r = idx & 127;
                sm.xs[d][r] = __ldg(&xb[(size_t)(dc + d) * TT + r]);
            }
            #pragma unroll
            for (int i = 0; i < (DC * KTILE) / NTH; i++) {
                int idx = tid + i * NTH;
                int kk2 = idx >> 5, d = idx & 31;
                sm.u.ws[d][kk2] = __ldg(&w[(size_t)(kt + kk2) * DD + dc + d]);
            }
            __syncthreads();
            #pragma unroll
            for (int d = 0; d < DC; d++) {
                // x row-pairs: direct LDS.64 of adjacent rows
                ull xp0 = *(const ull*)&sm.xs[d][8 * tr + 0];
                ull xp1 = *(const ull*)&sm.xs[d][8 * tr + 2];
                ull xp2 = *(const ull*)&sm.xs[d][8 * tr + 4];
                ull xp3 = *(const ull*)&sm.xs[d][8 * tr + 6];
                float4 b0 = *(const float4*)&sm.u.ws[d][8 * tc];
                float4 b1 = *(const float4*)&sm.u.ws[d][8 * tc + 4];
                ull wb[8];
                wb[0] = pack2(b0.x, b0.x); wb[1] = pack2(b0.y, b0.y);
                wb[2] = pack2(b0.z, b0.z); wb[3] = pack2(b0.w, b0.w);
                wb[4] = pack2(b1.x, b1.x); wb[5] = pack2(b1.y, b1.y);
                wb[6] = pack2(b1.z, b1.z); wb[7] = pack2(b1.w, b1.w);
                #pragma unroll
                for (int j = 0; j < 8; j++) {
                    ffma2(acc2[0][j], xp0, wb[j]);
                    ffma2(acc2[1][j], xp1, wb[j]);
                    ffma2(acc2[2][j], xp2, wb[j]);
                    ffma2(acc2[3][j], xp3, wb[j]);
                }
            }
        }
        __syncthreads();   // acc done; safe to overlay red onto ws

        float acc[8][8];
        #pragma unroll
        for (int ip = 0; ip < 4; ip++)
            #pragma unroll
            for (int j = 0; j < 8; j++)
                unpack2(acc2[ip][j], acc[2 * ip][j], acc[2 * ip + 1][j]);

        float wn8[8];
        #pragma unroll
        for (int j = 0; j < 8; j++) wn8[j] = g_wnorm[kt + 8 * tc + j];

        // dist = fl(fl(xn + wn) - 2*dot), exactly as reference rounds it
        #pragma unroll
        for (int i = 0; i < 8; i++) {
            float bs = INFINITY; int bi = kt + 8 * tc;
            #pragma unroll
            for (int j = 0; j < 8; j++) {
                int k = kt + 8 * tc + j;
                float t1 = __fadd_rn(xnr[i], wn8[j]);
                float s  = __fmaf_rn(-2.f, acc[i][j], t1);
                if (s < bs) { bs = s; bi = k; }
            }
            sm.u.red.S[8 * tr + i][tc] = bs;
            sm.u.red.I[8 * tr + i][tc] = bi;
        }
        __syncthreads();
        if (tid < ROWS) {
            float bs = sm.bestS[tid]; int bi = sm.bestI[tid];
            #pragma unroll
            for (int c = 0; c < 16; c++) {
                float s = sm.u.red.S[tid][c]; int ii = sm.u.red.I[tid][c];
                if (s < bs || (s == bs && ii < bi)) { bs = s; bi = ii; }
            }
            sm.bestS[tid] = bs; sm.bestI[tid] = bi;
        }
        __syncthreads();
    }

    // loss partial: bestS IS the row's sum (q-x)^2 (= xn + wn - 2 x.w)
    float part = (tid < ROWS) ? sm.bestS[tid] : 0.f;
    #pragma unroll
    for (int o = 16; o; o >>= 1) part += __shfl_xor_sync(0xffffffffu, part, o);
    if ((tid & 31) == 0) sm.rbuf[tid >> 5] = part;
    __syncthreads();
    if (tid == 0) {
        float s = 0.f;
        #pragma unroll
        for (int i = 0; i < 8; i++) s += sm.rbuf[i];
        atomicAdd(&g_acc, (double)s);
    }
    if (tid < ROWS) {
        int bi = sm.bestI[tid];
        atomicAdd(&g_counts[bi], 1);
        out[OUT_IDX + (size_t)(b * TT + t0 + tid)] = (float)bi;
    }
    #pragma unroll 4
    for (int i = tid; i < ROWS * DD; i += NTH) {
        int r = i >> 8, d = i & 255;
        out[((size_t)(b * TT + t0 + r)) * DD + d] = w[(size_t)sm.bestI[r] * DD + d];
    }
}

// ---------------- finalize: loss + perplexity ----------------
__global__ void vq_final(float* __restrict__ out) {
    __shared__ float sh[32];
    int tid = threadIdx.x;    // 1024 threads, one per code
    float p = (float)g_counts[tid] / (float)NN;
    float t = p * logf(p + 1e-10f);
    #pragma unroll
    for (int o = 16; o; o >>= 1) t += __shfl_xor_sync(0xffffffffu, t, o);
    if ((tid & 31) == 0) sh[tid >> 5] = t;
    __syncthreads();
    if (tid < 32) {
        float v = sh[tid];
        #pragma unroll
        for (int o = 16; o; o >>= 1) v += __shfl_xor_sync(0xffffffffu, v, o);
        if (tid == 0) {
            out[OUT_PERP] = expf(-v);
            out[OUT_LOSS] = (float)(1.25 * g_acc / ((double)NN * (double)DD));
        }
    }
}

extern "C" void kernel_launch(void* const* d_in, const int* in_sizes, int n_in,
                              void* d_out, int out_size) {
    const float* x = (const float*)d_in[0];   // [16, 256, 4096] fp32
    const float* w = (const float*)d_in[1];   // [1024, 256] fp32
    float* out = (float*)d_out;
    vq_xnorm<<<NN / 256, 256>>>(x);           // per-row ||x||^2 (order A)
    vq_prep<<<(KK * 32) / NTH, NTH>>>(w);     // wnorm + zero scratch
    vq_main<<<NN / ROWS, NTH>>>(x, w, out);   // 512 blocks
    vq_final<<<1, KK>>>(out);
}

// round 8
// speedup vs baseline: 2.5080x; 2.4128x over previous
#include <cuda_runtime.h>
#include <cuda_bf16.h>
#include <math.h>

#define BB 16
#define DD 256
#define TT 4096
#define NN (BB*TT)      // 65536 rows
#define KK 1024         // codes
#define ROWS 128        // rows per CTA
#define NTH 256
#define NCHUNK 64       // codes per pass
#define NPASS (KK/NCHUNK)   // 16
#define KSTEPS (DD/16)      // 16
#define MARGIN 8e-5f

#define OUT_LOSS ((size_t)NN*DD)
#define OUT_PERP (OUT_LOSS+1)
#define OUT_IDX  (OUT_PERP+1)

// padded smem row: 256 bf16 + 8 pad = 264 halves = 528 B (132 words; 132%32=4 -> conflict-free ldmatrix)
#define RSTR 528
#define SM_WN    0                      // 1024 floats = 4096 B
#define SM_A_HI  4096                   // 128*528 = 67584 B
#define SM_A_LO  (SM_A_HI + 67584)
#define SM_B_HI  (SM_A_LO + 67584)      // 64*528 = 33792 B
#define SM_B_LO  (SM_B_HI + 33792)
#define SM_TOTAL (SM_B_LO + 33792)      // 206848 B

typedef unsigned int u32;

__device__ float  g_wnorm[KK];
__device__ float  g_xnorm[NN];
__device__ int    g_counts[KK];
__device__ double g_acc;
__device__ int    g_bestI[NN];
__device__ float  g_bestS[NN];
__device__ int    g_amb[NN];
__device__ int    g_namb;
__device__ __nv_bfloat16 g_whi[KK * DD];   // plain [k][d]
__device__ __nv_bfloat16 g_wlo[KK * DD];

__device__ __forceinline__ u32 smem_u32(const void* p) {
    u32 a; asm("{ .reg .u64 t; cvta.to.shared.u64 t, %1; cvt.u32.u64 %0, t; }" : "=r"(a) : "l"(p));
    return a;
}
__device__ __forceinline__ void ldsm4(u32& r0, u32& r1, u32& r2, u32& r3, u32 addr) {
    asm volatile("ldmatrix.sync.aligned.m8n8.x4.shared.b16 {%0,%1,%2,%3}, [%4];"
        : "=r"(r0), "=r"(r1), "=r"(r2), "=r"(r3) : "r"(addr));
}
__device__ __forceinline__ void ldsm2(u32& r0, u32& r1, u32 addr) {
    asm volatile("ldmatrix.sync.aligned.m8n8.x2.shared.b16 {%0,%1}, [%2];"
        : "=r"(r0), "=r"(r1) : "r"(addr));
}
__device__ __forceinline__ void mma_bf16(float* c, u32 a0, u32 a1, u32 a2, u32 a3, u32 b0, u32 b1) {
    asm volatile("mma.sync.aligned.m16n8k16.row.col.f32.bf16.bf16.f32 "
        "{%0,%1,%2,%3}, {%4,%5,%6,%7}, {%8,%9}, {%0,%1,%2,%3};"
        : "+f"(c[0]), "+f"(c[1]), "+f"(c[2]), "+f"(c[3])
        : "r"(a0), "r"(a1), "r"(a2), "r"(a3), "r"(b0), "r"(b1));
}
__device__ __forceinline__ void upd(float s, int j, float& bs, int& bi, float& ss) {
    if (s < bs) { ss = bs; bs = s; bi = j; }
    else if (s < ss) ss = s;
}
__device__ __forceinline__ void qmerge(float& bs, int& bi, float& ss, int m) {
    float obs = __shfl_xor_sync(0xffffffffu, bs, m);
    int   obi = __shfl_xor_sync(0xffffffffu, bi, m);
    float oss = __shfl_xor_sync(0xffffffffu, ss, m);
    if (obs < bs || (obs == bs && obi < bi)) { ss = fminf(bs, oss); bs = obs; bi = obi; }
    else ss = fminf(ss, fminf(obs, oss));
}

// ---------------- prep: wnorm, zero scratch ----------------
__global__ void vq_prep(const float* __restrict__ w) {
    int gt   = blockIdx.x * blockDim.x + threadIdx.x;
    int warp = gt >> 5, lane = gt & 31;
    const float* wr = w + (size_t)warp * DD;
    float s = 0.f;
    #pragma unroll
    for (int d = lane; d < DD; d += 32) { float v = wr[d]; s = __fmaf_rn(v, v, s); }
    #pragma unroll
    for (int o = 16; o; o >>= 1) s = __fadd_rn(s, __shfl_xor_sync(0xffffffffu, s, o));
    if (lane == 0) g_wnorm[warp] = s;
    if (gt < KK) g_counts[gt] = 0;
    if (gt == 0) { g_acc = 0.0; g_namb = 0; }
}

// ---------------- prep: w -> bf16 hi/lo (plain layout) ----------------
__global__ __launch_bounds__(256) void vq_prep_w(const float* __restrict__ w) {
    int idx = blockIdx.x * 256 + threadIdx.x;       // 0..262143
    float v = __ldg(&w[idx]);
    __nv_bfloat16 hi = __float2bfloat16(v);
    __nv_bfloat16 lo = __float2bfloat16(__fadd_rn(v, -__bfloat162float(hi)));
    g_whi[idx] = hi;
    g_wlo[idx] = lo;
}

// ---------------- xnorm: per-row sum(x^2), GPU warp-reduce order ----------
__global__ __launch_bounds__(256) void vq_xnorm(const float* __restrict__ x) {
    int r = blockIdx.x * blockDim.x + threadIdx.x;
    int b = r >> 12, t = r & 4095;
    const float* xp = x + (size_t)b * (DD * TT) + t;
    float pA[32];
    #pragma unroll
    for (int l = 0; l < 32; l++) pA[l] = 0.f;
    #pragma unroll 1
    for (int i = 0; i < 8; i++) {
        #pragma unroll
        for (int l = 0; l < 32; l++) {
            float v = __ldg(&xp[(size_t)(i * 32 + l) * TT]);
            pA[l] = __fadd_rn(pA[l], __fmul_rn(v, v));
        }
    }
    #pragma unroll
    for (int l = 0; l < 16; l++) pA[l] = __fadd_rn(pA[l], pA[l + 16]);
    #pragma unroll
    for (int l = 0; l < 8; l++)  pA[l] = __fadd_rn(pA[l], pA[l + 8]);
    #pragma unroll
    for (int l = 0; l < 4; l++)  pA[l] = __fadd_rn(pA[l], pA[l + 4]);
    pA[0] = __fadd_rn(pA[0], pA[2]); pA[1] = __fadd_rn(pA[1], pA[3]);
    g_xnorm[r] = __fadd_rn(pA[0], pA[1]);
}

// ---------------- main: mma.sync bf16x2-split distance GEMM + argmin -------
__global__ void __launch_bounds__(NTH, 1) vq_main_mma(const float* __restrict__ x) {
    extern __shared__ char smem[];
    u32 sb = smem_u32(smem);
    int tid = threadIdx.x, wid = tid >> 5, lane = tid & 31;
    int cta = blockIdx.x;
    int b = cta >> 5, t0 = (cta & 31) * ROWS;

    float* wn = (float*)(smem + SM_WN);
    #pragma unroll
    for (int i = tid; i < KK; i += NTH) wn[i] = g_wnorm[i];

    // load + convert + store A (x tile) into padded smem, bf16 hi/lo
    {
        const float* xb = x + (size_t)b * DD * TT + t0;
        int r = tid & 127, half = tid >> 7;
        #pragma unroll 4
        for (int it = 0; it < 64; it++) {
            int d = it * 4 + half * 2;
            float v0 = __ldg(&xb[(size_t)d * TT + r]);
            float v1 = __ldg(&xb[(size_t)(d + 1) * TT + r]);
            __nv_bfloat16 h0 = __float2bfloat16(v0);
            __nv_bfloat16 h1 = __float2bfloat16(v1);
            __nv_bfloat16 l0 = __float2bfloat16(__fadd_rn(v0, -__bfloat162float(h0)));
            __nv_bfloat16 l1 = __float2bfloat16(__fadd_rn(v1, -__bfloat162float(h1)));
            u32 hp = (u32)__bfloat16_as_ushort(h0) | ((u32)__bfloat16_as_ushort(h1) << 16);
            u32 lp = (u32)__bfloat16_as_ushort(l0) | ((u32)__bfloat16_as_ushort(l1) << 16);
            u32 byte = (u32)(r * RSTR + d * 2);
            *(u32*)(smem + SM_A_HI + byte) = hp;
            *(u32*)(smem + SM_A_LO + byte) = lp;
        }
    }

    int g = lane >> 2, q = lane & 3;
    int r0 = wid * 16 + g, r1 = r0 + 8;
    float xn0 = g_xnorm[(size_t)b * TT + t0 + r0];
    float xn1 = g_xnorm[(size_t)b * TT + t0 + r1];
    float bs0 = INFINITY, ss0 = INFINITY, bs1 = INFINITY, ss1 = INFINITY;
    int bi0 = 0, bi1 = 0;

    u32 aHi = sb + SM_A_HI + (u32)(wid * 16 * RSTR) + (u32)((lane & 15) * RSTR + (lane >> 4) * 16);
    u32 aLo = sb + SM_A_LO + (u32)(wid * 16 * RSTR) + (u32)((lane & 15) * RSTR + (lane >> 4) * 16);
    u32 bOffL = (u32)((lane & 7) * RSTR + ((lane >> 3) & 1) * 16);

    for (int pass = 0; pass < NPASS; pass++) {
        __syncthreads();   // previous pass's ldmatrix done before overwriting B
        {
            const uint4* shh = (const uint4*)g_whi + (size_t)pass * NCHUNK * 32;
            const uint4* sll = (const uint4*)g_wlo + (size_t)pass * NCHUNK * 32;
            #pragma unroll
            for (int i = tid; i < NCHUNK * 32; i += NTH) {
                int row = i >> 5, c = i & 31;
                *(uint4*)(smem + SM_B_HI + row * RSTR + c * 16) = __ldg(&shh[i]);
                *(uint4*)(smem + SM_B_LO + row * RSTR + c * 16) = __ldg(&sll[i]);
            }
        }
        __syncthreads();

        float acc[8][4];
        #pragma unroll
        for (int nt = 0; nt < 8; nt++)
            #pragma unroll
            for (int c = 0; c < 4; c++) acc[nt][c] = 0.f;

        #pragma unroll 4
        for (int ks = 0; ks < KSTEPS; ks++) {
            u32 ah0, ah1, ah2, ah3, al0, al1, al2, al3;
            ldsm4(ah0, ah1, ah2, ah3, aHi + ks * 32);
            ldsm4(al0, al1, al2, al3, aLo + ks * 32);
            #pragma unroll
            for (int nt = 0; nt < 8; nt++) {
                u32 bh0, bh1, bl0, bl1;
                u32 bo = (u32)(nt * 8 * RSTR) + bOffL + ks * 32;
                ldsm2(bh0, bh1, sb + SM_B_HI + bo);
                ldsm2(bl0, bl1, sb + SM_B_LO + bo);
                mma_bf16(acc[nt], ah0, ah1, ah2, ah3, bh0, bh1);
                mma_bf16(acc[nt], ah0, ah1, ah2, ah3, bl0, bl1);
                mma_bf16(acc[nt], al0, al1, al2, al3, bh0, bh1);
            }
        }
        // epilogue: dist = fl(fl(xn+wn) - 2*dot), best/second-best, ascending j
        int kb = pass * NCHUNK;
        #pragma unroll
        for (int nt = 0; nt < 8; nt++) {
            int j = kb + nt * 8 + q * 2;
            float w0 = wn[j], w1 = wn[j + 1];
            upd(__fmaf_rn(-2.f, acc[nt][0], __fadd_rn(xn0, w0)), j,     bs0, bi0, ss0);
            upd(__fmaf_rn(-2.f, acc[nt][1], __fadd_rn(xn0, w1)), j + 1, bs0, bi0, ss0);
            upd(__fmaf_rn(-2.f, acc[nt][2], __fadd_rn(xn1, w0)), j,     bs1, bi1, ss1);
            upd(__fmaf_rn(-2.f, acc[nt][3], __fadd_rn(xn1, w1)), j + 1, bs1, bi1, ss1);
        }
    }

    // quad reduce (lanes sharing the same rows)
    qmerge(bs0, bi0, ss0, 1); qmerge(bs0, bi0, ss0, 2);
    qmerge(bs1, bi1, ss1, 1); qmerge(bs1, bi1, ss1, 2);
    if (q == 0) {
        int row0 = b * TT + t0 + r0, row1 = b * TT + t0 + r1;
        g_bestI[row0] = bi0; g_bestS[row0] = bs0;
        g_bestI[row1] = bi1; g_bestS[row1] = bs1;
        if (ss0 < bs0 + MARGIN) { int p = atomicAdd(&g_namb, 1); g_amb[p] = row0; }
        if (ss1 < bs1 + MARGIN) { int p = atomicAdd(&g_namb, 1); g_amb[p] = row1; }
    }
}

// ---------------- refine: exact fp32 full re-scan of ambiguous rows --------
__global__ void __launch_bounds__(256) vq_refine(const float* __restrict__ x,
                                                 const float* __restrict__ w) {
    __shared__ float xs[8][256];
    __shared__ float wch[32][257];
    int tid = threadIdx.x, rl = tid >> 5, lane = tid & 31;
    int namb = g_namb;
    for (int batch = blockIdx.x; batch * 8 < namb; batch += gridDim.x) {
        int row = -1;
        int ai = batch * 8 + rl;
        if (ai < namb) row = g_amb[ai];
        if (row >= 0) {
            int b = row >> 12, t = row & 4095;
            for (int d = lane; d < 256; d += 32)
                xs[rl][d] = __ldg(&x[(size_t)b * DD * TT + (size_t)d * TT + t]);
        }
        float xn = (row >= 0) ? g_xnorm[row] : 0.f;
        float best = INFINITY; int bi = 0;
        for (int kt = 0; kt < KK; kt += 32) {
            __syncthreads();
            #pragma unroll
            for (int i = tid; i < 32 * 256; i += 256)
                wch[i >> 8][i & 255] = __ldg(&w[(size_t)(kt + (i >> 8)) * 256 + (i & 255)]);
            __syncthreads();
            if (row >= 0) {
                float acc = 0.f;
                #pragma unroll 8
                for (int d = 0; d < 256; d++)
                    acc = __fmaf_rn(xs[rl][d], wch[lane][d], acc);
                int k = kt + lane;
                float t1 = __fadd_rn(xn, g_wnorm[k]);
                float s  = __fmaf_rn(-2.f, acc, t1);
                if (s < best) { best = s; bi = k; }   // per-lane ks ascending
            }
        }
        #pragma unroll
        for (int o = 16; o; o >>= 1) {
            float so = __shfl_xor_sync(0xffffffffu, best, o);
            int   io = __shfl_xor_sync(0xffffffffu, bi, o);
            if (so < best || (so == best && io < bi)) { best = so; bi = io; }
        }
        if (row >= 0 && lane == 0) g_bestI[row] = bi;
        __syncthreads();
    }
}

// ---------------- output: gather + histogram + loss sum ----------------
__global__ void __launch_bounds__(256) vq_out(const float* __restrict__ w,
                                              float* __restrict__ out) {
    __shared__ int idx[ROWS];
    __shared__ float rb[8];
    int tid = threadIdx.x, cta = blockIdx.x;
    int b = cta >> 5, t0 = (cta & 31) * ROWS;
    float part = 0.f;
    if (tid < ROWS) {
        int row = b * TT + t0 + tid;
        int k = g_bestI[row];
        idx[tid] = k;
        atomicAdd(&g_counts[k], 1);
        out[OUT_IDX + (size_t)row] = (float)k;
        part = g_bestS[row];
    }
    #pragma unroll
    for (int o = 16; o; o >>= 1) part += __shfl_xor_sync(0xffffffffu, part, o);
    if ((tid & 31) == 0) rb[tid >> 5] = part;
    __syncthreads();
    if (tid == 0) {
        float s = 0.f;
        #pragma unroll
        for (int i = 0; i < 8; i++) s += rb[i];
        atomicAdd(&g_acc, (double)s);
    }
    #pragma unroll 4
    for (int i = tid; i < ROWS * DD; i += 256) {
        int r = i >> 8, d = i & 255;
        out[((size_t)(b * TT + t0 + r)) * DD + d] = __ldg(&w[(size_t)idx[r] * DD + d]);
    }
}

// ---------------- finalize: loss + perplexity ----------------
__global__ void vq_final(float* __restrict__ out) {
    __shared__ float sh[32];
    int tid = threadIdx.x;
    float p = (float)g_counts[tid] / (float)NN;
    float t = p * logf(p + 1e-10f);
    #pragma unroll
    for (int o = 16; o; o >>= 1) t += __shfl_xor_sync(0xffffffffu, t, o);
    if ((tid & 31) == 0) sh[tid >> 5] = t;
    __syncthreads();
    if (tid < 32) {
        float v = sh[tid];
        #pragma unroll
        for (int o = 16; o; o >>= 1) v += __shfl_xor_sync(0xffffffffu, v, o);
        if (tid == 0) {
            out[OUT_PERP] = expf(-v);
            out[OUT_LOSS] = (float)(1.25 * g_acc / ((double)NN * (double)DD));
        }
    }
}

extern "C" void kernel_launch(void* const* d_in, const int* in_sizes, int n_in,
                              void* d_out, int out_size) {
    const float* x = (const float*)d_in[0];   // [16, 256, 4096] fp32
    const float* w = (const float*)d_in[1];   // [1024, 256] fp32
    float* out = (float*)d_out;
    cudaFuncSetAttribute(vq_main_mma, cudaFuncAttributeMaxDynamicSharedMemorySize, SM_TOTAL);
    vq_prep<<<(KK * 32) / NTH, NTH>>>(w);          // wnorm + zero scratch
    vq_prep_w<<<(KK * DD) / 256, 256>>>(w);        // bf16 hi/lo codebook
    vq_xnorm<<<NN / 256, 256>>>(x);                // per-row ||x||^2 (order A)
    vq_main_mma<<<NN / ROWS, NTH, SM_TOTAL>>>(x);  // 512 CTAs, HMMA scoring
    vq_refine<<<256, 256>>>(x, w);                 // exact re-scan of ambiguous rows
    vq_out<<<NN / ROWS, 256>>>(w, out);            // gather + hist + loss
    vq_final<<<1, KK>>>(out);
}